// round 14
// baseline (speedup 1.0000x reference)
#include <cuda_runtime.h>
#include <math.h>

#define BB 64
#define PP 8732
#define OO 32
#define CC 81
#define IMGF 224.0f
#define SEG 13
#define CHUNK 672           // 13*672 = 8736 >= 8732
#define PPAD 9216           // 9*1024, padded loop bound for full-warp sync
#define FULL 0xffffffffu

// ------------- device scratch (zero-initialized at load; self-cleaning) -------------
__device__ unsigned char      g_obj[BB * PP];   // bit7 = positive flag, bits 0..4 = obj
__device__ unsigned char      g_cls[BB * PP];
__device__ float              g_lse[BB * PP];
__device__ float              g_sc[BB * PP];    // scores[bp][cls] gathered in k_match
__device__ unsigned long long g_pfo[BB * OO];   // zeroed by k_conf after use
__device__ int                g_npos[BB];       // zeroed by last k_conf block
__device__ float              g_acc[4];         // 0:sl1 1:posce 2:hardnegce; zeroed by last block
__device__ int                g_counter;        // block-completion ticket; reset by last block

__device__ __forceinline__ float smooth_l1_4(float cx, float cy, float cw, float ch,
                                             float4 pr, float4 pl) {
    float gx = (cx - pr.x) / (pr.z / 10.0f);
    float gy = (cy - pr.y) / (pr.w / 10.0f);
    float gw = logf(cw / pr.z) * 5.0f;
    float gh = logf(ch / pr.w) * 5.0f;
    float d, s = 0.0f;
    d = fabsf(pl.x - gx); s += (d < 1.0f) ? 0.5f * d * d : d - 0.5f;
    d = fabsf(pl.y - gy); s += (d < 1.0f) ? 0.5f * d * d : d - 0.5f;
    d = fabsf(pl.z - gw); s += (d < 1.0f) ? 0.5f * d * d : d - 0.5f;
    d = fabsf(pl.w - gh); s += (d < 1.0f) ? 0.5f * d * d : d - 0.5f;
    return s;
}

// ---------------- kernel A: division-free matching + labels + loc + score gather ----------------
// IoU compares via cross-multiplication (all num/den > 0): a/b > c/d <=> a*d > c*b.
// Per-prior argmax: (bnum,bden,bobj) registers. Positivity: 2*bnum >= bden.
// Per-object max: lane o holds object o's running (num,den,p); a cheap warp-wide
// bound test (shfl lane o's bound + ballot) gates a rare cross-mult butterfly.
// End of kernel: ONE IEEE division per (warp,object) builds key iou_bits<<32|~p
// (rounded value -> inter-block tie semantics match jnp.argmax; ~p -> lowest p).
// Exact-vs-rounded compare differences are confined to ~1-ulp ties (measure-zero).
__global__ void __launch_bounds__(256, 5) k_match(const float* __restrict__ gt_boxes,
                                                  const int*   __restrict__ gt_labels,
                                                  const float* __restrict__ priors,
                                                  const float* __restrict__ pred_locs,
                                                  const float* __restrict__ scores) {
    int b   = blockIdx.x / SEG;
    int seg = blockIdx.x % SEG;
    __shared__ float4 sbox[OO];    // x1,y1,x2,y2
    __shared__ float4 scb[OO];     // cx,cy,w,h
    __shared__ int    slab[OO];
    __shared__ unsigned long long skey[OO];
    __shared__ float  swarp[8];
    __shared__ int    siwarp[8];
    int t = threadIdx.x, lane = t & 31;
    if (t < OO) {
        const float* g = gt_boxes + (b * OO + t) * 4;
        float x = g[0], y = g[1], w = g[2], h = g[3];
        float x1 = x / IMGF, y1 = y / IMGF;
        float x2 = (x + w) / IMGF, y2 = (y + h) / IMGF;
        sbox[t] = make_float4(x1, y1, x2, y2);
        scb[t]  = make_float4((x1 + x2) * 0.5f, (y1 + y2) * 0.5f, x2 - x1, y2 - y1);
        slab[t] = gt_labels[b * OO + t];
        skey[t] = 0ull;
    }
    __syncthreads();

    int p0 = seg * CHUNK;
    int p1 = p0 + CHUNK; if (p1 > PP) p1 = PP;

    // lane tracks object `lane`: running max ratio rnum/rden at prior rp
    float rnum = 0.0f, rden = 1.0f;
    int   rp   = 0;
    bool  rupd = false;
    int   npos = 0;
    float sl1  = 0.0f;

    for (int pb = p0 + (t - lane); pb < p1; pb += 256) {
        int  p  = pb + lane;
        bool vp = (p < p1);
        int  pc = vp ? p : (p1 - 1);
        float4 pr = ((const float4*)priors)[pc];
        float px1 = pr.x - pr.z * 0.5f, py1 = pr.y - pr.w * 0.5f;
        float px2 = pr.x + pr.z * 0.5f, py2 = pr.y + pr.w * 0.5f;
        float pa  = (px2 - px1) * (py2 - py1);
        float bnum = 0.0f, bden = 1.0f;
        int   bobj = 0;
#pragma unroll 4
        for (int o = 0; o < OO; o++) {
            float4 ob = sbox[o];
            float lx = fmaxf(ob.x, px1), ly = fmaxf(ob.y, py1);
            float rx = fminf(ob.z, px2), ry = fminf(ob.w, py2);
            float w_ = fmaxf(rx - lx, 0.0f), h_ = fmaxf(ry - ly, 0.0f);
            float num = w_ * h_;
            float oar = (ob.z - ob.x) * (ob.w - ob.y);
            float den = oar + pa - num;
            if (!vp) num = 0.0f;
            // per-prior argmax over o (strict >: first/lowest o wins on exact tie)
            if (num * bden > bnum * den) { bnum = num; bden = den; bobj = o; }
            // per-object bound test: does any lane beat object o's running max?
            float gn = __shfl_sync(FULL, rnum, o);
            float gd = __shfl_sync(FULL, rden, o);
            unsigned msk = __ballot_sync(FULL, num * gd > gn * den);
            if (msk) {
                // butterfly: max ratio, tie -> min p (lanes ordered by p)
                float tn = num, td = den; int tp_ = p;
#pragma unroll
                for (int off = 16; off; off >>= 1) {
                    float on = __shfl_xor_sync(FULL, tn,  off);
                    float od = __shfl_xor_sync(FULL, td,  off);
                    int   op = __shfl_xor_sync(FULL, tp_, off);
                    float l = on * td, r2 = tn * od;
                    bool take = (l > r2) || (l == r2 && op < tp_);
                    if (take) { tn = on; td = od; tp_ = op; }
                }
                if (lane == o) {
                    float l = tn * rden, r2 = rnum * td;
                    if (l > r2) { rnum = tn; rden = td; rp = tp_; rupd = true; }
                }
            }
        }
        if (vp) {
            int bp = b * PP + p;
            bool pos = (2.0f * bnum >= bden);            // ratio >= 0.5
            g_obj[bp] = (unsigned char)(bobj | (pos ? 0x80 : 0));
            int cls = pos ? slab[bobj] : 0;
            g_cls[bp] = (unsigned char)cls;
            g_sc[bp]  = scores[(size_t)bp * CC + cls];   // gather hides under compute
            if (pos) {
                npos++;
                float4 cb = scb[bobj];
                sl1 += smooth_l1_4(cb.x, cb.y, cb.z, cb.w,
                                   pr, ((const float4*)pred_locs)[bp]);
            }
        }
    }
#pragma unroll
    for (int off = 16; off; off >>= 1) {
        sl1  += __shfl_xor_sync(FULL, sl1,  off);
        npos += __shfl_xor_sync(FULL, npos, off);
    }
    if (lane == 0) { swarp[t >> 5] = sl1; siwarp[t >> 5] = npos; }
    __syncthreads();
    if (t == 0) {
        float S = 0.0f; int N = 0;
        for (int i = 0; i < 8; i++) { S += swarp[i]; N += siwarp[i]; }
        if (S != 0.0f) atomicAdd(&g_acc[0], S);
        if (N)         atomicAdd(&g_npos[b], N);
    }
    // per-object key: one correctly-rounded IEEE division per (warp, object)
    if (rupd) {
        float iou = rnum / rden;
        unsigned long long key = ((unsigned long long)__float_as_uint(iou) << 32)
                               | (unsigned long long)(0xFFFFFFFFu - (unsigned int)rp);
        atomicMax(&skey[lane], key);
    }
    __syncthreads();
    if (t < OO && skey[t] != 0ull) atomicMax(&g_pfo[b * OO + t], skey[t]);
}

// ---------------- kernel B: log-sum-exp, warp per 4 rows, no smem, MLP 12 ----------------
__global__ void __launch_bounds__(256) k_lse(const float* __restrict__ scores) {
    int warp = (int)((blockIdx.x * 256 + threadIdx.x) >> 5);
    int lane = threadIdx.x & 31;
    int row0 = warp * 4;
    if (row0 >= BB * PP) return;
    const float* r = scores + (size_t)row0 * CC;
    bool tail = (lane < CC - 64);
    float v0[4], v1[4], v2[4];
#pragma unroll
    for (int j = 0; j < 4; j++) {
        const float* rr = r + j * CC;
        v0[j] = rr[lane];
        v1[j] = rr[lane + 32];
        v2[j] = tail ? rr[lane + 64] : 0.0f;
    }
    float s[4];
#pragma unroll
    for (int j = 0; j < 4; j++) {
        s[j] = __expf(v0[j]) + __expf(v1[j]);
        if (tail) s[j] += __expf(v2[j]);
    }
#pragma unroll
    for (int off = 16; off; off >>= 1)
#pragma unroll
        for (int j = 0; j < 4; j++)
            s[j] += __shfl_xor_sync(FULL, s[j], off);
    if (lane == 0) {
        float4 o;
        o.x = __logf(s[0]); o.y = __logf(s[1]);
        o.z = __logf(s[2]); o.w = __logf(s[3]);
        *(float4*)(g_lse + row0) = o;
    }
}

// -------- kernel C: per-image forced-fix + CE + radix top-k + last-block finalize --------
__global__ void __launch_bounds__(1024) k_conf(const float* __restrict__ scores,
                                               const float* __restrict__ gt_boxes,
                                               const int*   __restrict__ gt_labels,
                                               const float* __restrict__ priors,
                                               const float* __restrict__ pred_locs,
                                               float* __restrict__ out) {
    int b = blockIdx.x;
    __shared__ float sce[PP];
    __shared__ int hist[256];
    __shared__ unsigned int s_prefix;
    __shared__ int s_K;
    __shared__ float swarp[32];
    __shared__ int s_last;
    int t = threadIdx.x;

    // ---- forced-assignment delta patch (warp 0; lane = object) ----
    if (t < 32) {
        int lane = t;
        const float* g = gt_boxes + (b * OO + lane) * 4;
        float x = g[0], y = g[1], w = g[2], h = g[3];
        float x1 = x / IMGF, y1 = y / IMGF;
        float x2 = (x + w) / IMGF, y2 = (y + h) / IMGF;
        float cx = (x1 + x2) * 0.5f, cy = (y1 + y2) * 0.5f;
        float cw = x2 - x1, ch = y2 - y1;
        int lab = gt_labels[b * OO + lane];

        unsigned long long kk = g_pfo[b * OO + lane];
        g_pfo[b * OO + lane] = 0ull;          // self-clean for next replay
        int p = (kk == 0ull) ? 0
              : (int)(0xFFFFFFFFu - (unsigned int)(kk & 0xFFFFFFFFull));
        unsigned int m = __match_any_sync(FULL, p);
        bool winner = (lane == 31 - __clz(m));
        int bp = b * PP + p;

        unsigned char ob = g_obj[bp];
        int  obj_old = ob & 31;
        bool pos_old = (ob & 0x80) != 0;
        float ocx = __shfl_sync(FULL, cx, obj_old);
        float ocy = __shfl_sync(FULL, cy, obj_old);
        float ocw = __shfl_sync(FULL, cw, obj_old);
        float och = __shfl_sync(FULL, ch, obj_old);

        float dsl1 = 0.0f;
        int   dnp  = 0;
        if (winner) {
            float4 pr = ((const float4*)priors)[p];
            float4 pl = ((const float4*)pred_locs)[bp];
            if (pos_old) {
                dsl1 -= smooth_l1_4(ocx, ocy, ocw, och, pr, pl);
                dnp  -= 1;
            }
            dsl1 += smooth_l1_4(cx, cy, cw, ch, pr, pl);
            dnp  += 1;
            g_cls[bp] = (unsigned char)lab;                       // forced: foreground
            g_sc[bp]  = scores[(size_t)bp * CC + lab];            // patch gathered score
        }
#pragma unroll
        for (int off = 16; off; off >>= 1) {
            dsl1 += __shfl_xor_sync(FULL, dsl1, off);
            dnp  += __shfl_xor_sync(FULL, dnp,  off);
        }
        if (lane == 0) {
            if (dsl1 != 0.0f) atomicAdd(&g_acc[0], dsl1);
            if (dnp)          atomicAdd(&g_npos[b], dnp);
        }
    }
    __syncthreads();   // patches + dnp visible to whole block

    // ---- CE from pre-gathered linear arrays ----
    float pos = 0.0f;
    for (int i = t; i < PP; i += 1024) {
        int bp = b * PP + i;
        int cls = g_cls[bp];
        float ce = g_lse[bp] - g_sc[bp];
        if (cls != 0) { sce[i] = 0.0f; pos += ce; }
        else          { sce[i] = ce; }
    }
#pragma unroll
    for (int off = 16; off; off >>= 1) pos += __shfl_xor_sync(FULL, pos, off);
    if ((t & 31) == 0) swarp[t >> 5] = pos;
    __syncthreads();
    if (t == 0) {
        float S = 0.0f;
        for (int w = 0; w < 32; w++) S += swarp[w];
        if (S != 0.0f) atomicAdd(&g_acc[1], S);
        int np = g_npos[b];
        int k = 3 * ((np > 1) ? np : 1);
        if (k > PP) k = PP;
        s_prefix = 0u; s_K = k;
    }
    __syncthreads();

    // ---- radix-select top-k over smem (warp-aggregated histogram atomics) ----
    for (int byte = 3; byte >= 0; --byte) {
        if (t < 256) hist[t] = 0;
        __syncthreads();
        unsigned int pref = s_prefix;
        for (int i = t; i < PPAD; i += 1024) {
            bool valid = (i < PP);
            unsigned int u = valid ? __float_as_uint(sce[i]) : 0u;
            bool ok = valid && ((byte == 3) || ((u >> ((byte + 1) * 8)) == pref));
            int bin = ok ? (int)((u >> (byte * 8)) & 255) : -1;
            unsigned int m = __match_any_sync(FULL, bin);
            if (ok && (t & 31) == (__ffs(m) - 1))
                atomicAdd(&hist[bin], __popc(m));
        }
        __syncthreads();
        if (t == 0) {
            int K = s_K, cum = 0, sel = 0;
            for (int bin = 255; bin >= 0; --bin) {
                cum += hist[bin];
                if (cum >= K) { sel = bin; K -= (cum - hist[bin]); break; }
            }
            s_prefix = (s_prefix << 8) | (unsigned int)sel;
            s_K = K;
        }
        __syncthreads();
    }
    unsigned int tb = s_prefix;
    float tv = __uint_as_float(tb);
    float sum = 0.0f;
    for (int i = t; i < PP; i += 1024) {
        float v = sce[i];
        if (__float_as_uint(v) > tb) sum += v;
    }
#pragma unroll
    for (int off = 16; off; off >>= 1) sum += __shfl_xor_sync(FULL, sum, off);
    if ((t & 31) == 0) swarp[t >> 5] = sum;
    __syncthreads();
    if (t == 0) {
        float S = 0.0f;
        for (int i = 0; i < 32; i++) S += swarp[i];
        S += (float)s_K * tv;
        atomicAdd(&g_acc[2], S);
    }

    // ---- last block finalizes and self-cleans scratch ----
    __syncthreads();
    if (t == 0) {
        __threadfence();
        int ticket = atomicAdd(&g_counter, 1);
        s_last = (ticket == BB - 1) ? 1 : 0;
    }
    __syncthreads();
    if (s_last) {
        if (t < 32) {
            int n1 = atomicAdd(&g_npos[t], 0);
            int n2 = atomicAdd(&g_npos[t + 32], 0);
            int tp = n1 + n2;
            float ncl = (float)((n1 > 1) ? n1 : 1) + (float)((n2 > 1) ? n2 : 1);
#pragma unroll
            for (int off = 16; off; off >>= 1) {
                tp  += __shfl_xor_sync(FULL, tp,  off);
                ncl += __shfl_xor_sync(FULL, ncl, off);
            }
            if (t == 0) {
                float a0 = atomicAdd(&g_acc[0], 0.0f);
                float a1 = atomicAdd(&g_acc[1], 0.0f);
                float a2 = atomicAdd(&g_acc[2], 0.0f);
                float loc = 0.0f;
                if (tp > 0) loc = a0 / (float)(tp * 4);
                out[0] = (a1 + a2) / ncl + loc;
            }
        }
        __syncthreads();
        if (t < BB) g_npos[t] = 0;
        if (t < 4)  g_acc[t] = 0.0f;
        if (t == 0) g_counter = 0;
    }
}

// ---------------- launch: fork LSE || match, join into conf ----------------
extern "C" void kernel_launch(void* const* d_in, const int* in_sizes, int n_in,
                              void* d_out, int out_size) {
    const float* pred_locs   = (const float*)d_in[0];
    const float* pred_scores = (const float*)d_in[1];
    const float* gt_boxes    = (const float*)d_in[2];
    const int*   gt_labels   = (const int*)d_in[3];
    const float* priors      = (const float*)d_in[4];
    float* out = (float*)d_out;

    static cudaStream_t s2 = 0;
    static cudaEvent_t  evF = 0, evJ = 0;
    if (s2 == 0) {
        cudaStreamCreateWithFlags(&s2, cudaStreamNonBlocking);
        cudaEventCreateWithFlags(&evF, cudaEventDisableTiming);
        cudaEventCreateWithFlags(&evJ, cudaEventDisableTiming);
    }

    // fork: LSE branch depends on nothing (warp per 4 rows)
    cudaEventRecord(evF, 0);
    cudaStreamWaitEvent(s2, evF, 0);
    k_lse<<<(BB * PP + 31) / 32, 256, 0, s2>>>(pred_scores);
    cudaEventRecord(evJ, s2);

    // main-stream matching (division-free, fused score gather)
    k_match<<<BB * SEG, 256>>>(gt_boxes, gt_labels, priors, pred_locs, pred_scores);

    // join, then fused fix + CE + mining + finalize
    cudaStreamWaitEvent(0, evJ, 0);
    k_conf<<<BB, 1024>>>(pred_scores, gt_boxes, gt_labels, priors, pred_locs, out);
}

// round 15
// speedup vs baseline: 1.2358x; 1.2358x over previous
#include <cuda_runtime.h>
#include <math.h>

#define BB 64
#define PP 8732
#define OO 32
#define CC 81
#define IMGF 224.0f
#define SEG 13
#define CHUNK 672           // 13*672 = 8736 >= 8732
#define PPAD 9216           // 9*1024, padded loop bound for full-warp sync
#define FULL 0xffffffffu

// ------------- device scratch (zero-initialized at load; self-cleaning) -------------
__device__ unsigned char      g_obj[BB * PP];   // bit7 = positive flag, bits 0..4 = obj
__device__ unsigned char      g_cls[BB * PP];
__device__ float              g_lse[BB * PP];
__device__ float              g_sc[BB * PP];    // scores[bp][cls] gathered in k_match
__device__ unsigned long long g_pfo[BB * OO];   // zeroed by k_conf after use
__device__ int                g_npos[BB];       // zeroed by last k_conf block
__device__ float              g_acc[4];         // 0:sl1 1:posce 2:hardnegce; zeroed by last block
__device__ int                g_counter;        // block-completion ticket; reset by last block

__device__ __forceinline__ float smooth_l1_4(float cx, float cy, float cw, float ch,
                                             float4 pr, float4 pl) {
    float gx = (cx - pr.x) / (pr.z / 10.0f);
    float gy = (cy - pr.y) / (pr.w / 10.0f);
    float gw = logf(cw / pr.z) * 5.0f;
    float gh = logf(ch / pr.w) * 5.0f;
    float d, s = 0.0f;
    d = fabsf(pl.x - gx); s += (d < 1.0f) ? 0.5f * d * d : d - 0.5f;
    d = fabsf(pl.y - gy); s += (d < 1.0f) ? 0.5f * d * d : d - 0.5f;
    d = fabsf(pl.z - gw); s += (d < 1.0f) ? 0.5f * d * d : d - 0.5f;
    d = fabsf(pl.w - gh); s += (d < 1.0f) ? 0.5f * d * d : d - 0.5f;
    return s;
}

// ---------- kernel A: matching + labels + loc + score gather (division only on improvement) ----------
// Per-prior argmax via cross-multiplication (all num/den > 0): a/b > c/d <=> a*d > c*b.
// Scalar ops only in the inner loop — no MUFU, no warp collectives.
// Per-object running max: smem u64 key (iou_bits<<32 | ~p). Guard reads the hi
// word as a float bound; IEEE division runs ONLY when the candidate beats the
// bound (rare after warm-up), so key bits are correctly rounded and ties resolve
// to lowest p exactly as in R13 (rel_err 8e-8). Stale bound reads are safe
// (monotone max). Rational-vs-rounded compare flips are ~1-ulp measure-zero.
__global__ void __launch_bounds__(256, 5) k_match(const float* __restrict__ gt_boxes,
                                                  const int*   __restrict__ gt_labels,
                                                  const float* __restrict__ priors,
                                                  const float* __restrict__ pred_locs,
                                                  const float* __restrict__ scores) {
    int b   = blockIdx.x / SEG;
    int seg = blockIdx.x % SEG;
    __shared__ float4 sbox[OO];    // x1,y1,x2,y2
    __shared__ float  sar[OO];
    __shared__ float4 scb[OO];     // cx,cy,w,h
    __shared__ int    slab[OO];
    __shared__ unsigned long long skey[OO];
    __shared__ float  swarp[8];
    __shared__ int    siwarp[8];
    const unsigned int* shi = (const unsigned int*)skey;   // [2*o+1] = hi word (iou bits)
    int t = threadIdx.x;
    if (t < OO) {
        const float* g = gt_boxes + (b * OO + t) * 4;
        float x = g[0], y = g[1], w = g[2], h = g[3];
        float x1 = x / IMGF, y1 = y / IMGF;
        float x2 = (x + w) / IMGF, y2 = (y + h) / IMGF;
        sbox[t] = make_float4(x1, y1, x2, y2);
        sar[t]  = (x2 - x1) * (y2 - y1);
        scb[t]  = make_float4((x1 + x2) * 0.5f, (y1 + y2) * 0.5f, x2 - x1, y2 - y1);
        slab[t] = gt_labels[b * OO + t];
        skey[t] = 0ull;
    }
    __syncthreads();

    int p0 = seg * CHUNK;
    int p1 = p0 + CHUNK; if (p1 > PP) p1 = PP;
    int   npos = 0;
    float sl1  = 0.0f;
    for (int p = p0 + t; p < p1; p += 256) {
        float4 pr = ((const float4*)priors)[p];
        float px1 = pr.x - pr.z * 0.5f, py1 = pr.y - pr.w * 0.5f;
        float px2 = pr.x + pr.z * 0.5f, py2 = pr.y + pr.w * 0.5f;
        float pa  = (px2 - px1) * (py2 - py1);
        float bnum = 0.0f, bden = 1.0f;
        int   bobj = 0;
        unsigned long long lowp = (unsigned long long)(0xFFFFFFFFu - (unsigned int)p);
#pragma unroll 8
        for (int o = 0; o < OO; o++) {
            float4 ob = sbox[o];
            float lx = fmaxf(ob.x, px1), ly = fmaxf(ob.y, py1);
            float rx = fminf(ob.z, px2), ry = fminf(ob.w, py2);
            float w_ = fmaxf(rx - lx, 0.0f), h_ = fmaxf(ry - ly, 0.0f);
            float num = w_ * h_;
            float den = sar[o] + pa - num;
            // per-prior argmax over o: cross-multiplied strict > (first max wins)
            if (num * bden > bnum * den) { bnum = num; bden = den; bobj = o; }
            // per-object improvement guard: float bound from key hi word
            float bound = __uint_as_float(shi[2 * o + 1]);
            if (num > 0.0f && num >= bound * den) {
                float iou = num / den;                 // IEEE, rare: only on improvement
                atomicMax(&skey[o],
                          ((unsigned long long)__float_as_uint(iou) << 32) | lowp);
            }
        }
        int bp = b * PP + p;
        bool pos = (2.0f * bnum >= bden);              // ratio >= 0.5
        g_obj[bp] = (unsigned char)(bobj | (pos ? 0x80 : 0));
        int cls = pos ? slab[bobj] : 0;
        g_cls[bp] = (unsigned char)cls;
        g_sc[bp]  = scores[(size_t)bp * CC + cls];     // gather hides under compute
        if (pos) {
            npos++;
            float4 cb = scb[bobj];
            sl1 += smooth_l1_4(cb.x, cb.y, cb.z, cb.w,
                               pr, ((const float4*)pred_locs)[bp]);
        }
    }
#pragma unroll
    for (int off = 16; off; off >>= 1) {
        sl1  += __shfl_xor_sync(FULL, sl1,  off);
        npos += __shfl_xor_sync(FULL, npos, off);
    }
    if ((t & 31) == 0) { swarp[t >> 5] = sl1; siwarp[t >> 5] = npos; }
    __syncthreads();
    if (t == 0) {
        float S = 0.0f; int N = 0;
        for (int i = 0; i < 8; i++) { S += swarp[i]; N += siwarp[i]; }
        if (S != 0.0f) atomicAdd(&g_acc[0], S);
        if (N)         atomicAdd(&g_npos[b], N);
    }
    __syncthreads();
    if (t < OO && skey[t] != 0ull) atomicMax(&g_pfo[b * OO + t], skey[t]);
}

// ---------------- kernel B: log-sum-exp, warp per 4 rows, no smem, MLP 12 ----------------
__global__ void __launch_bounds__(256) k_lse(const float* __restrict__ scores) {
    int warp = (int)((blockIdx.x * 256 + threadIdx.x) >> 5);
    int lane = threadIdx.x & 31;
    int row0 = warp * 4;
    if (row0 >= BB * PP) return;
    const float* r = scores + (size_t)row0 * CC;
    bool tail = (lane < CC - 64);
    float v0[4], v1[4], v2[4];
#pragma unroll
    for (int j = 0; j < 4; j++) {
        const float* rr = r + j * CC;
        v0[j] = rr[lane];
        v1[j] = rr[lane + 32];
        v2[j] = tail ? rr[lane + 64] : 0.0f;
    }
    float s[4];
#pragma unroll
    for (int j = 0; j < 4; j++) {
        s[j] = __expf(v0[j]) + __expf(v1[j]);
        if (tail) s[j] += __expf(v2[j]);
    }
#pragma unroll
    for (int off = 16; off; off >>= 1)
#pragma unroll
        for (int j = 0; j < 4; j++)
            s[j] += __shfl_xor_sync(FULL, s[j], off);
    if (lane == 0) {
        float4 o;
        o.x = __logf(s[0]); o.y = __logf(s[1]);
        o.z = __logf(s[2]); o.w = __logf(s[3]);
        *(float4*)(g_lse + row0) = o;
    }
}

// -------- kernel C: per-image forced-fix + CE + radix top-k + last-block finalize --------
__global__ void __launch_bounds__(1024) k_conf(const float* __restrict__ scores,
                                               const float* __restrict__ gt_boxes,
                                               const int*   __restrict__ gt_labels,
                                               const float* __restrict__ priors,
                                               const float* __restrict__ pred_locs,
                                               float* __restrict__ out) {
    int b = blockIdx.x;
    __shared__ float sce[PP];
    __shared__ int hist[256];
    __shared__ unsigned int s_prefix;
    __shared__ int s_K;
    __shared__ float swarp[32];
    __shared__ int s_last;
    int t = threadIdx.x;

    // ---- forced-assignment delta patch (warp 0; lane = object) ----
    if (t < 32) {
        int lane = t;
        const float* g = gt_boxes + (b * OO + lane) * 4;
        float x = g[0], y = g[1], w = g[2], h = g[3];
        float x1 = x / IMGF, y1 = y / IMGF;
        float x2 = (x + w) / IMGF, y2 = (y + h) / IMGF;
        float cx = (x1 + x2) * 0.5f, cy = (y1 + y2) * 0.5f;
        float cw = x2 - x1, ch = y2 - y1;
        int lab = gt_labels[b * OO + lane];

        unsigned long long kk = g_pfo[b * OO + lane];
        g_pfo[b * OO + lane] = 0ull;          // self-clean for next replay
        int p = (kk == 0ull) ? 0
              : (int)(0xFFFFFFFFu - (unsigned int)(kk & 0xFFFFFFFFull));
        unsigned int m = __match_any_sync(FULL, p);
        bool winner = (lane == 31 - __clz(m));
        int bp = b * PP + p;

        unsigned char ob = g_obj[bp];
        int  obj_old = ob & 31;
        bool pos_old = (ob & 0x80) != 0;
        float ocx = __shfl_sync(FULL, cx, obj_old);
        float ocy = __shfl_sync(FULL, cy, obj_old);
        float ocw = __shfl_sync(FULL, cw, obj_old);
        float och = __shfl_sync(FULL, ch, obj_old);

        float dsl1 = 0.0f;
        int   dnp  = 0;
        if (winner) {
            float4 pr = ((const float4*)priors)[p];
            float4 pl = ((const float4*)pred_locs)[bp];
            if (pos_old) {
                dsl1 -= smooth_l1_4(ocx, ocy, ocw, och, pr, pl);
                dnp  -= 1;
            }
            dsl1 += smooth_l1_4(cx, cy, cw, ch, pr, pl);
            dnp  += 1;
            g_cls[bp] = (unsigned char)lab;                       // forced: foreground
            g_sc[bp]  = scores[(size_t)bp * CC + lab];            // patch gathered score
        }
#pragma unroll
        for (int off = 16; off; off >>= 1) {
            dsl1 += __shfl_xor_sync(FULL, dsl1, off);
            dnp  += __shfl_xor_sync(FULL, dnp,  off);
        }
        if (lane == 0) {
            if (dsl1 != 0.0f) atomicAdd(&g_acc[0], dsl1);
            if (dnp)          atomicAdd(&g_npos[b], dnp);
        }
    }
    __syncthreads();   // patches + dnp visible to whole block

    // ---- CE from pre-gathered linear arrays ----
    float pos = 0.0f;
    for (int i = t; i < PP; i += 1024) {
        int bp = b * PP + i;
        int cls = g_cls[bp];
        float ce = g_lse[bp] - g_sc[bp];
        if (cls != 0) { sce[i] = 0.0f; pos += ce; }
        else          { sce[i] = ce; }
    }
#pragma unroll
    for (int off = 16; off; off >>= 1) pos += __shfl_xor_sync(FULL, pos, off);
    if ((t & 31) == 0) swarp[t >> 5] = pos;
    __syncthreads();
    if (t == 0) {
        float S = 0.0f;
        for (int w = 0; w < 32; w++) S += swarp[w];
        if (S != 0.0f) atomicAdd(&g_acc[1], S);
        int np = g_npos[b];
        int k = 3 * ((np > 1) ? np : 1);
        if (k > PP) k = PP;
        s_prefix = 0u; s_K = k;
    }
    __syncthreads();

    // ---- radix-select top-k over smem (warp-aggregated histogram atomics) ----
    for (int byte = 3; byte >= 0; --byte) {
        if (t < 256) hist[t] = 0;
        __syncthreads();
        unsigned int pref = s_prefix;
        for (int i = t; i < PPAD; i += 1024) {
            bool valid = (i < PP);
            unsigned int u = valid ? __float_as_uint(sce[i]) : 0u;
            bool ok = valid && ((byte == 3) || ((u >> ((byte + 1) * 8)) == pref));
            int bin = ok ? (int)((u >> (byte * 8)) & 255) : -1;
            unsigned int m = __match_any_sync(FULL, bin);
            if (ok && (t & 31) == (__ffs(m) - 1))
                atomicAdd(&hist[bin], __popc(m));
        }
        __syncthreads();
        if (t == 0) {
            int K = s_K, cum = 0, sel = 0;
            for (int bin = 255; bin >= 0; --bin) {
                cum += hist[bin];
                if (cum >= K) { sel = bin; K -= (cum - hist[bin]); break; }
            }
            s_prefix = (s_prefix << 8) | (unsigned int)sel;
            s_K = K;
        }
        __syncthreads();
    }
    unsigned int tb = s_prefix;
    float tv = __uint_as_float(tb);
    float sum = 0.0f;
    for (int i = t; i < PP; i += 1024) {
        float v = sce[i];
        if (__float_as_uint(v) > tb) sum += v;
    }
#pragma unroll
    for (int off = 16; off; off >>= 1) sum += __shfl_xor_sync(FULL, sum, off);
    if ((t & 31) == 0) swarp[t >> 5] = sum;
    __syncthreads();
    if (t == 0) {
        float S = 0.0f;
        for (int i = 0; i < 32; i++) S += swarp[i];
        S += (float)s_K * tv;
        atomicAdd(&g_acc[2], S);
    }

    // ---- last block finalizes and self-cleans scratch ----
    __syncthreads();
    if (t == 0) {
        __threadfence();
        int ticket = atomicAdd(&g_counter, 1);
        s_last = (ticket == BB - 1) ? 1 : 0;
    }
    __syncthreads();
    if (s_last) {
        if (t < 32) {
            int n1 = atomicAdd(&g_npos[t], 0);
            int n2 = atomicAdd(&g_npos[t + 32], 0);
            int tp = n1 + n2;
            float ncl = (float)((n1 > 1) ? n1 : 1) + (float)((n2 > 1) ? n2 : 1);
#pragma unroll
            for (int off = 16; off; off >>= 1) {
                tp  += __shfl_xor_sync(FULL, tp,  off);
                ncl += __shfl_xor_sync(FULL, ncl, off);
            }
            if (t == 0) {
                float a0 = atomicAdd(&g_acc[0], 0.0f);
                float a1 = atomicAdd(&g_acc[1], 0.0f);
                float a2 = atomicAdd(&g_acc[2], 0.0f);
                float loc = 0.0f;
                if (tp > 0) loc = a0 / (float)(tp * 4);
                out[0] = (a1 + a2) / ncl + loc;
            }
        }
        __syncthreads();
        if (t < BB) g_npos[t] = 0;
        if (t < 4)  g_acc[t] = 0.0f;
        if (t == 0) g_counter = 0;
    }
}

// ---------------- launch: fork LSE || match, join into conf ----------------
extern "C" void kernel_launch(void* const* d_in, const int* in_sizes, int n_in,
                              void* d_out, int out_size) {
    const float* pred_locs   = (const float*)d_in[0];
    const float* pred_scores = (const float*)d_in[1];
    const float* gt_boxes    = (const float*)d_in[2];
    const int*   gt_labels   = (const int*)d_in[3];
    const float* priors      = (const float*)d_in[4];
    float* out = (float*)d_out;

    static cudaStream_t s2 = 0;
    static cudaEvent_t  evF = 0, evJ = 0;
    if (s2 == 0) {
        cudaStreamCreateWithFlags(&s2, cudaStreamNonBlocking);
        cudaEventCreateWithFlags(&evF, cudaEventDisableTiming);
        cudaEventCreateWithFlags(&evJ, cudaEventDisableTiming);
    }

    // fork: LSE branch depends on nothing (warp per 4 rows)
    cudaEventRecord(evF, 0);
    cudaStreamWaitEvent(s2, evF, 0);
    k_lse<<<(BB * PP + 31) / 32, 256, 0, s2>>>(pred_scores);
    cudaEventRecord(evJ, s2);

    // main-stream matching (division only on improvement, fused score gather)
    k_match<<<BB * SEG, 256>>>(gt_boxes, gt_labels, priors, pred_locs, pred_scores);

    // join, then fused fix + CE + mining + finalize
    cudaStreamWaitEvent(0, evJ, 0);
    k_conf<<<BB, 1024>>>(pred_scores, gt_boxes, gt_labels, priors, pred_locs, out);
}

// round 16
// speedup vs baseline: 1.2771x; 1.0334x over previous
#include <cuda_runtime.h>
#include <math.h>

#define BB 64
#define PP 8732
#define OO 32
#define CC 81
#define IMGF 224.0f
#define SEG 13
#define CHUNK 672           // 13*672 = 8736 >= 8732
#define LSEB 273            // lse blocks per image: 273*32 = 8736 >= 8732 rows
#define PPAD 9216           // 9*1024, padded loop bound for full-warp sync
#define FULL 0xffffffffu

// ------------- device scratch (zero-initialized at load; self-cleaning) -------------
__device__ unsigned char      g_obj[BB * PP];   // bit7 = positive flag, bits 0..4 = obj
__device__ unsigned char      g_cls[BB * PP];
__device__ float              g_lse[BB * PP];
__device__ float              g_sc[BB * PP];    // scores[bp][cls] gathered in k_match
__device__ unsigned long long g_pfo[BB * OO];   // zeroed by k_conf after use
__device__ int                g_npos[BB];       // zeroed by last k_conf block
__device__ float              g_acc[4];         // 0:sl1 1:posce 2:hardnegce; zeroed by last block
__device__ int                g_counter;        // block-completion ticket; reset by last block
__device__ int                g_mdone[BB];      // match blocks done per image; reset by k_conf
__device__ int                g_ldone[BB];      // lse blocks done per image; reset by k_conf

__device__ __forceinline__ float smooth_l1_4(float cx, float cy, float cw, float ch,
                                             float4 pr, float4 pl) {
    float gx = (cx - pr.x) / (pr.z / 10.0f);
    float gy = (cy - pr.y) / (pr.w / 10.0f);
    float gw = logf(cw / pr.z) * 5.0f;
    float gh = logf(ch / pr.w) * 5.0f;
    float d, s = 0.0f;
    d = fabsf(pl.x - gx); s += (d < 1.0f) ? 0.5f * d * d : d - 0.5f;
    d = fabsf(pl.y - gy); s += (d < 1.0f) ? 0.5f * d * d : d - 0.5f;
    d = fabsf(pl.z - gw); s += (d < 1.0f) ? 0.5f * d * d : d - 0.5f;
    d = fabsf(pl.w - gh); s += (d < 1.0f) ? 0.5f * d * d : d - 0.5f;
    return s;
}

// ---------- kernel A: matching + labels + loc + score gather (division only on improvement) ----------
__global__ void __launch_bounds__(256, 5) k_match(const float* __restrict__ gt_boxes,
                                                  const int*   __restrict__ gt_labels,
                                                  const float* __restrict__ priors,
                                                  const float* __restrict__ pred_locs,
                                                  const float* __restrict__ scores) {
    int b   = blockIdx.x / SEG;
    int seg = blockIdx.x % SEG;
    __shared__ float4 sbox[OO];    // x1,y1,x2,y2
    __shared__ float  sar[OO];
    __shared__ float4 scb[OO];     // cx,cy,w,h
    __shared__ int    slab[OO];
    __shared__ unsigned long long skey[OO];
    __shared__ float  swarp[8];
    __shared__ int    siwarp[8];
    const unsigned int* shi = (const unsigned int*)skey;   // [2*o+1] = hi word (iou bits)
    int t = threadIdx.x;
    if (t < OO) {
        const float* g = gt_boxes + (b * OO + t) * 4;
        float x = g[0], y = g[1], w = g[2], h = g[3];
        float x1 = x / IMGF, y1 = y / IMGF;
        float x2 = (x + w) / IMGF, y2 = (y + h) / IMGF;
        sbox[t] = make_float4(x1, y1, x2, y2);
        sar[t]  = (x2 - x1) * (y2 - y1);
        scb[t]  = make_float4((x1 + x2) * 0.5f, (y1 + y2) * 0.5f, x2 - x1, y2 - y1);
        slab[t] = gt_labels[b * OO + t];
        skey[t] = 0ull;
    }
    __syncthreads();

    int p0 = seg * CHUNK;
    int p1 = p0 + CHUNK; if (p1 > PP) p1 = PP;
    int   npos = 0;
    float sl1  = 0.0f;
    for (int p = p0 + t; p < p1; p += 256) {
        float4 pr = ((const float4*)priors)[p];
        float px1 = pr.x - pr.z * 0.5f, py1 = pr.y - pr.w * 0.5f;
        float px2 = pr.x + pr.z * 0.5f, py2 = pr.y + pr.w * 0.5f;
        float pa  = (px2 - px1) * (py2 - py1);
        float bnum = 0.0f, bden = 1.0f;
        int   bobj = 0;
        unsigned long long lowp = (unsigned long long)(0xFFFFFFFFu - (unsigned int)p);
#pragma unroll 8
        for (int o = 0; o < OO; o++) {
            float4 ob = sbox[o];
            float lx = fmaxf(ob.x, px1), ly = fmaxf(ob.y, py1);
            float rx = fminf(ob.z, px2), ry = fminf(ob.w, py2);
            float w_ = fmaxf(rx - lx, 0.0f), h_ = fmaxf(ry - ly, 0.0f);
            float num = w_ * h_;
            float den = sar[o] + pa - num;
            // per-prior argmax over o: cross-multiplied strict > (first max wins)
            if (num * bden > bnum * den) { bnum = num; bden = den; bobj = o; }
            // per-object improvement guard: float bound from key hi word
            float bound = __uint_as_float(shi[2 * o + 1]);
            if (num > 0.0f && num >= bound * den) {
                float iou = num / den;                 // IEEE, rare: only on improvement
                atomicMax(&skey[o],
                          ((unsigned long long)__float_as_uint(iou) << 32) | lowp);
            }
        }
        int bp = b * PP + p;
        bool pos = (2.0f * bnum >= bden);              // ratio >= 0.5
        g_obj[bp] = (unsigned char)(bobj | (pos ? 0x80 : 0));
        int cls = pos ? slab[bobj] : 0;
        g_cls[bp] = (unsigned char)cls;
        g_sc[bp]  = scores[(size_t)bp * CC + cls];     // gather hides under compute
        if (pos) {
            npos++;
            float4 cb = scb[bobj];
            sl1 += smooth_l1_4(cb.x, cb.y, cb.z, cb.w,
                               pr, ((const float4*)pred_locs)[bp]);
        }
    }
#pragma unroll
    for (int off = 16; off; off >>= 1) {
        sl1  += __shfl_xor_sync(FULL, sl1,  off);
        npos += __shfl_xor_sync(FULL, npos, off);
    }
    if ((t & 31) == 0) { swarp[t >> 5] = sl1; siwarp[t >> 5] = npos; }
    __syncthreads();
    if (t == 0) {
        float S = 0.0f; int N = 0;
        for (int i = 0; i < 8; i++) { S += swarp[i]; N += siwarp[i]; }
        if (S != 0.0f) atomicAdd(&g_acc[0], S);
        if (N)         atomicAdd(&g_npos[b], N);
    }
    __syncthreads();
    if (t < OO && skey[t] != 0ull) atomicMax(&g_pfo[b * OO + t], skey[t]);
    // signal: this image's match block done (threadFenceReduction idiom)
    __syncthreads();
    if (t == 0) { __threadfence(); atomicAdd(&g_mdone[b], 1); }
}

// ---------------- kernel B: log-sum-exp, warp per 4 rows, per-image blocks ----------------
// 8732 = 272*32 + 28: every warp handles exactly 4 rows or is fully idle.
__global__ void __launch_bounds__(256) k_lse(const float* __restrict__ scores) {
    int b = blockIdx.x / LSEB;
    int j = blockIdx.x % LSEB;
    int warp = threadIdx.x >> 5, lane = threadIdx.x & 31;
    int rin = j * 32 + warp * 4;
    if (rin + 4 <= PP) {
        int row0 = b * PP + rin;
        const float* r = scores + (size_t)row0 * CC;
        bool tail = (lane < CC - 64);
        float v0[4], v1[4], v2[4];
#pragma unroll
        for (int k = 0; k < 4; k++) {
            const float* rr = r + k * CC;
            v0[k] = rr[lane];
            v1[k] = rr[lane + 32];
            v2[k] = tail ? rr[lane + 64] : 0.0f;
        }
        float s[4];
#pragma unroll
        for (int k = 0; k < 4; k++) {
            s[k] = __expf(v0[k]) + __expf(v1[k]);
            if (tail) s[k] += __expf(v2[k]);
        }
#pragma unroll
        for (int off = 16; off; off >>= 1)
#pragma unroll
            for (int k = 0; k < 4; k++)
                s[k] += __shfl_xor_sync(FULL, s[k], off);
        if (lane == 0) {
            float4 o;
            o.x = __logf(s[0]); o.y = __logf(s[1]);
            o.z = __logf(s[2]); o.w = __logf(s[3]);
            *(float4*)(g_lse + row0) = o;
        }
    }
    __syncthreads();
    if (threadIdx.x == 0) { __threadfence(); atomicAdd(&g_ldone[b], 1); }
}

// -------- kernel C: spin on per-image producers, then fix + CE + top-k + finalize --------
// Launched concurrently (no stream edge): block b starts as soon as ITS image's
// 13 match blocks and 273 lse blocks are done -> conf overlaps the parallel phase.
__global__ void __launch_bounds__(1024) k_conf(const float* __restrict__ scores,
                                               const float* __restrict__ gt_boxes,
                                               const int*   __restrict__ gt_labels,
                                               const float* __restrict__ priors,
                                               const float* __restrict__ pred_locs,
                                               float* __restrict__ out) {
    int b = blockIdx.x;
    __shared__ float sce[PP];
    __shared__ int hist[256];
    __shared__ unsigned int s_prefix;
    __shared__ int s_K;
    __shared__ float swarp[32];
    __shared__ int s_last;
    int t = threadIdx.x;

    // ---- wait for this image's producers (device-side dependency) ----
    if (t == 0) {
        while (atomicAdd(&g_mdone[b], 0) < SEG)  __nanosleep(128);
        while (atomicAdd(&g_ldone[b], 0) < LSEB) __nanosleep(128);
        __threadfence();
        g_mdone[b] = 0;            // self-clean for next replay
        g_ldone[b] = 0;
    }
    __syncthreads();

    // ---- forced-assignment delta patch (warp 0; lane = object) ----
    if (t < 32) {
        int lane = t;
        const float* g = gt_boxes + (b * OO + lane) * 4;
        float x = g[0], y = g[1], w = g[2], h = g[3];
        float x1 = x / IMGF, y1 = y / IMGF;
        float x2 = (x + w) / IMGF, y2 = (y + h) / IMGF;
        float cx = (x1 + x2) * 0.5f, cy = (y1 + y2) * 0.5f;
        float cw = x2 - x1, ch = y2 - y1;
        int lab = gt_labels[b * OO + lane];

        unsigned long long kk = g_pfo[b * OO + lane];
        g_pfo[b * OO + lane] = 0ull;          // self-clean for next replay
        int p = (kk == 0ull) ? 0
              : (int)(0xFFFFFFFFu - (unsigned int)(kk & 0xFFFFFFFFull));
        unsigned int m = __match_any_sync(FULL, p);
        bool winner = (lane == 31 - __clz(m));
        int bp = b * PP + p;

        unsigned char ob = g_obj[bp];
        int  obj_old = ob & 31;
        bool pos_old = (ob & 0x80) != 0;
        float ocx = __shfl_sync(FULL, cx, obj_old);
        float ocy = __shfl_sync(FULL, cy, obj_old);
        float ocw = __shfl_sync(FULL, cw, obj_old);
        float och = __shfl_sync(FULL, ch, obj_old);

        float dsl1 = 0.0f;
        int   dnp  = 0;
        if (winner) {
            float4 pr = ((const float4*)priors)[p];
            float4 pl = ((const float4*)pred_locs)[bp];
            if (pos_old) {
                dsl1 -= smooth_l1_4(ocx, ocy, ocw, och, pr, pl);
                dnp  -= 1;
            }
            dsl1 += smooth_l1_4(cx, cy, cw, ch, pr, pl);
            dnp  += 1;
            g_cls[bp] = (unsigned char)lab;                       // forced: foreground
            g_sc[bp]  = scores[(size_t)bp * CC + lab];            // patch gathered score
        }
#pragma unroll
        for (int off = 16; off; off >>= 1) {
            dsl1 += __shfl_xor_sync(FULL, dsl1, off);
            dnp  += __shfl_xor_sync(FULL, dnp,  off);
        }
        if (lane == 0) {
            if (dsl1 != 0.0f) atomicAdd(&g_acc[0], dsl1);
            if (dnp)          atomicAdd(&g_npos[b], dnp);
        }
    }
    __syncthreads();   // patches + dnp visible to whole block

    // ---- CE from pre-gathered linear arrays ----
    float pos = 0.0f;
    for (int i = t; i < PP; i += 1024) {
        int bp = b * PP + i;
        int cls = g_cls[bp];
        float ce = g_lse[bp] - g_sc[bp];
        if (cls != 0) { sce[i] = 0.0f; pos += ce; }
        else          { sce[i] = ce; }
    }
#pragma unroll
    for (int off = 16; off; off >>= 1) pos += __shfl_xor_sync(FULL, pos, off);
    if ((t & 31) == 0) swarp[t >> 5] = pos;
    __syncthreads();
    if (t == 0) {
        float S = 0.0f;
        for (int w = 0; w < 32; w++) S += swarp[w];
        if (S != 0.0f) atomicAdd(&g_acc[1], S);
        int np = g_npos[b];
        int k = 3 * ((np > 1) ? np : 1);
        if (k > PP) k = PP;
        s_prefix = 0u; s_K = k;
    }
    __syncthreads();

    // ---- radix-select top-k over smem (warp-aggregated histogram atomics) ----
    for (int byte = 3; byte >= 0; --byte) {
        if (t < 256) hist[t] = 0;
        __syncthreads();
        unsigned int pref = s_prefix;
        for (int i = t; i < PPAD; i += 1024) {
            bool valid = (i < PP);
            unsigned int u = valid ? __float_as_uint(sce[i]) : 0u;
            bool ok = valid && ((byte == 3) || ((u >> ((byte + 1) * 8)) == pref));
            int bin = ok ? (int)((u >> (byte * 8)) & 255) : -1;
            unsigned int m = __match_any_sync(FULL, bin);
            if (ok && (t & 31) == (__ffs(m) - 1))
                atomicAdd(&hist[bin], __popc(m));
        }
        __syncthreads();
        if (t == 0) {
            int K = s_K, cum = 0, sel = 0;
            for (int bin = 255; bin >= 0; --bin) {
                cum += hist[bin];
                if (cum >= K) { sel = bin; K -= (cum - hist[bin]); break; }
            }
            s_prefix = (s_prefix << 8) | (unsigned int)sel;
            s_K = K;
        }
        __syncthreads();
    }
    unsigned int tb = s_prefix;
    float tv = __uint_as_float(tb);
    float sum = 0.0f;
    for (int i = t; i < PP; i += 1024) {
        float v = sce[i];
        if (__float_as_uint(v) > tb) sum += v;
    }
#pragma unroll
    for (int off = 16; off; off >>= 1) sum += __shfl_xor_sync(FULL, sum, off);
    if ((t & 31) == 0) swarp[t >> 5] = sum;
    __syncthreads();
    if (t == 0) {
        float S = 0.0f;
        for (int i = 0; i < 32; i++) S += swarp[i];
        S += (float)s_K * tv;
        atomicAdd(&g_acc[2], S);
    }

    // ---- last block finalizes and self-cleans scratch ----
    __syncthreads();
    if (t == 0) {
        __threadfence();
        int ticket = atomicAdd(&g_counter, 1);
        s_last = (ticket == BB - 1) ? 1 : 0;
    }
    __syncthreads();
    if (s_last) {
        if (t < 32) {
            int n1 = atomicAdd(&g_npos[t], 0);
            int n2 = atomicAdd(&g_npos[t + 32], 0);
            int tp = n1 + n2;
            float ncl = (float)((n1 > 1) ? n1 : 1) + (float)((n2 > 1) ? n2 : 1);
#pragma unroll
            for (int off = 16; off; off >>= 1) {
                tp  += __shfl_xor_sync(FULL, tp,  off);
                ncl += __shfl_xor_sync(FULL, ncl, off);
            }
            if (t == 0) {
                float a0 = atomicAdd(&g_acc[0], 0.0f);
                float a1 = atomicAdd(&g_acc[1], 0.0f);
                float a2 = atomicAdd(&g_acc[2], 0.0f);
                float loc = 0.0f;
                if (tp > 0) loc = a0 / (float)(tp * 4);
                out[0] = (a1 + a2) / ncl + loc;
            }
        }
        __syncthreads();
        if (t < BB) g_npos[t] = 0;
        if (t < 4)  g_acc[t] = 0.0f;
        if (t == 0) g_counter = 0;
    }
}

// ------- launch: match || lse || conf all concurrent; conf self-orders per image -------
extern "C" void kernel_launch(void* const* d_in, const int* in_sizes, int n_in,
                              void* d_out, int out_size) {
    const float* pred_locs   = (const float*)d_in[0];
    const float* pred_scores = (const float*)d_in[1];
    const float* gt_boxes    = (const float*)d_in[2];
    const int*   gt_labels   = (const int*)d_in[3];
    const float* priors      = (const float*)d_in[4];
    float* out = (float*)d_out;

    static cudaStream_t s2 = 0, s3 = 0;
    static cudaEvent_t  evF = 0, evL = 0, evM = 0;
    if (s2 == 0) {
        cudaStreamCreateWithFlags(&s2, cudaStreamNonBlocking);
        cudaStreamCreateWithFlags(&s3, cudaStreamNonBlocking);
        cudaEventCreateWithFlags(&evF, cudaEventDisableTiming);
        cudaEventCreateWithFlags(&evL, cudaEventDisableTiming);
        cudaEventCreateWithFlags(&evM, cudaEventDisableTiming);
    }

    // fork both producers
    cudaEventRecord(evF, 0);
    cudaStreamWaitEvent(s2, evF, 0);
    cudaStreamWaitEvent(s3, evF, 0);
    k_match<<<BB * SEG, 256, 0, s3>>>(gt_boxes, gt_labels, priors, pred_locs, pred_scores);
    cudaEventRecord(evM, s3);
    k_lse<<<BB * LSEB, 256, 0, s2>>>(pred_scores);
    cudaEventRecord(evL, s2);

    // consumer: no stream dependency — per-image spin on done counters
    k_conf<<<BB, 1024>>>(pred_scores, gt_boxes, gt_labels, priors, pred_locs, out);

    // join forks back for graph-capture completeness
    cudaStreamWaitEvent(0, evM, 0);
    cudaStreamWaitEvent(0, evL, 0);
}